// round 2
// baseline (speedup 1.0000x reference)
#include <cuda_runtime.h>
#include <math.h>

#define T_LEN 2048
#define BATCH 64
#define EMB   100
#define HID   128
#define G3    384   // 3*HID gate rows
#define NS    6     // CRF states
#define GRU_THREADS 384

// ---------------- device scratch (no allocation allowed) ----------------
__device__ float g_gi[2][T_LEN][G3];        // precomputed x@Wih^T + bih, per dir
__device__ float g_hout[2][T_LEN][HID];     // GRU hidden outputs, per dir
__device__ __align__(16) float g_logits[T_LEN * NS];  // softmax probs

// ---------------- f32x2 helpers (packed dual-FP32 FMA, sm_100+) ---------
__device__ __forceinline__ unsigned long long ffma2(unsigned long long a,
                                                    unsigned long long b,
                                                    unsigned long long c) {
    unsigned long long d;
    asm("fma.rn.f32x2 %0, %1, %2, %3;" : "=l"(d) : "l"(a), "l"(b), "l"(c));
    return d;
}
__device__ __forceinline__ unsigned long long pack2(float lo, float hi) {
    unsigned long long d;
    asm("mov.b64 %0, {%1, %2};" : "=l"(d) : "f"(lo), "f"(hi));
    return d;
}
__device__ __forceinline__ float2 unpack2(unsigned long long u) {
    float2 r;
    asm("mov.b64 {%0, %1}, %2;" : "=f"(r.x), "=f"(r.y) : "l"(u));
    return r;
}
__device__ __forceinline__ float sigmoidf_(float x) {
    return 1.0f / (1.0f + expf(-x));
}

// ---------------- cluster / mbarrier helpers -----------------------------
__device__ __forceinline__ unsigned int smem_u32(const void* p) {
    return (unsigned int)__cvta_generic_to_shared(p);
}
__device__ __forceinline__ unsigned int mapa_u32(unsigned int laddr,
                                                 unsigned int rank) {
    unsigned int r;
    asm("mapa.shared::cluster.u32 %0, %1, %2;" : "=r"(r) : "r"(laddr), "r"(rank));
    return r;
}
__device__ __forceinline__ void mbar_init(unsigned int mbar, unsigned int cnt) {
    asm volatile("mbarrier.init.shared.b64 [%0], %1;" :: "r"(mbar), "r"(cnt)
                 : "memory");
}
__device__ __forceinline__ void mbar_arrive_expect_tx(unsigned int mbar,
                                                      unsigned int bytes) {
    asm volatile("mbarrier.arrive.expect_tx.shared.b64 _, [%0], %1;"
                 :: "r"(mbar), "r"(bytes) : "memory");
}
__device__ __forceinline__ void mbar_wait_parity(unsigned int mbar,
                                                 unsigned int parity) {
    unsigned int done;
    asm volatile(
        "{\n\t.reg .pred p;\n\t"
        "mbarrier.try_wait.parity.acquire.cta.shared::cta.b64 p, [%1], %2;\n\t"
        "selp.b32 %0, 1, 0, p;\n\t}"
        : "=r"(done) : "r"(mbar), "r"(parity) : "memory");
    if (!done) {
        asm volatile(
            "{\n\t.reg .pred P1;\n\t"
            "WL_%=:\n\t"
            "mbarrier.try_wait.parity.acquire.cta.shared::cta.b64 P1, [%0], %1, 0x989680;\n\t"
            "@P1 bra.uni WD_%=;\n\t"
            "bra.uni WL_%=;\n\t"
            "WD_%=:\n\t}"
            :: "r"(mbar), "r"(parity) : "memory");
    }
}
__device__ __forceinline__ void st_async_remote_f32(unsigned int raddr, float v,
                                                    unsigned int rmbar) {
    asm volatile(
        "st.async.shared::cluster.mbarrier::complete_tx::bytes.b32 [%0], %1, [%2];"
        :: "r"(raddr), "r"(__float_as_uint(v)), "r"(rmbar) : "memory");
}
__device__ __forceinline__ void cluster_sync_() {
    asm volatile("barrier.cluster.arrive.aligned;" ::: "memory");
    asm volatile("barrier.cluster.wait.aligned;" ::: "memory");
}

// ================= Kernel 1: gi = x @ Wih^T + bih (batch row 63) =========
__global__ void __launch_bounds__(G3) gi_kernel(
    const int* __restrict__ sentence, const float* __restrict__ emb,
    const float* __restrict__ Wf_ih, const float* __restrict__ bf_ih,
    const float* __restrict__ Wb_ih, const float* __restrict__ bb_ih)
{
    const int dir = blockIdx.y;
    const int t0  = blockIdx.x * 4;
    __shared__ float x_s[4][EMB];

    for (int i = threadIdx.x; i < 4 * EMB; i += G3) {
        int tt = i / EMB, e = i % EMB;
        int tok = sentence[63 * T_LEN + t0 + tt];
        x_s[tt][e] = emb[tok * EMB + e];
    }
    __syncthreads();

    const float* W = dir ? Wb_ih : Wf_ih;
    const float* b = dir ? bb_ih : bf_ih;
    const int j = threadIdx.x;

    float bj = b[j];
    float a0 = bj, a1 = bj, a2 = bj, a3 = bj;
    const float* Wr = W + j * EMB;
#pragma unroll
    for (int e = 0; e < EMB; e++) {
        float w = __ldg(Wr + e);
        a0 += w * x_s[0][e];
        a1 += w * x_s[1][e];
        a2 += w * x_s[2][e];
        a3 += w * x_s[3][e];
    }
    g_gi[dir][t0 + 0][j] = a0;
    g_gi[dir][t0 + 1][j] = a1;
    g_gi[dir][t0 + 2][j] = a2;
    g_gi[dir][t0 + 3][j] = a3;
}

// ================= Kernel 2: GRU recurrence, 2-CTA cluster per direction ==
// grid 4, cluster 2. Clusters {0,1}=fwd, {2,3}=bwd. Each CTA owns 64 hidden
// units (192 gate rows), 2 threads per row (each half of the 128-dot).
// Per step the 64 new h values are pushed to the peer via st.async +
// mbarrier complete_tx (2 alternating mbarriers, double-buffered h).
__global__ void __launch_bounds__(GRU_THREADS, 1) __cluster_dims__(2, 1, 1)
gru_kernel(const float* __restrict__ Wf_hh, const float* __restrict__ bf_hh,
           const float* __restrict__ Wb_hh, const float* __restrict__ bb_hh,
           const float* __restrict__ h0)
{
    const int dir  = blockIdx.x >> 1;
    const int tid  = threadIdx.x;
    const int row  = tid >> 1;          // 0..191
    const int half = tid & 1;           // which 64-wide slice of h
    const int gate = row >> 6;          // 0=r,1=z,2=n
    const int jj   = row & 63;
    unsigned int rank;
    asm("mov.u32 %0, %%cluster_ctarank;" : "=r"(rank));
    const int j    = (int)rank * 64 + jj;   // hidden unit owned by this CTA
    const int grow = gate * 128 + j;        // global gate row

    __shared__ __align__(16) float h_buf[2][HID];
    __shared__ float r_s[64];
    __shared__ float z_s[64];
    __shared__ __align__(8) unsigned long long mbar[2];

    const unsigned int mb0 = smem_u32(&mbar[0]);
    const unsigned int mb1 = smem_u32(&mbar[1]);

    const float* Whh = dir ? Wb_hh : Wf_hh;
    const float* bhh = dir ? bb_hh : bf_hh;

    // half-row of weights (64 floats) as 32 packed f32x2 registers
    unsigned long long w[32];
    {
        const unsigned long long* Wr =
            reinterpret_cast<const unsigned long long*>(Whh + grow * 128 + half * 64);
#pragma unroll
        for (int k = 0; k < 32; k++) w[k] = __ldg(Wr + k);
    }
    const float bias = (half == 0) ? bhh[grow] : 0.0f;

    if (tid < HID) h_buf[0][tid] = h0[dir * (BATCH * HID) + 63 * HID + tid];
    if (tid == 0) { mbar_init(mb0, 1); mbar_init(mb1, 1); }
    __syncthreads();
    cluster_sync_();   // peer mbarriers initialized before any st.async

    // remote (peer CTA) addresses for h slot j in each buffer + both mbars
    const unsigned int peer = rank ^ 1u;
    const unsigned int rh0  = mapa_u32(smem_u32(&h_buf[0][j]), peer);
    const unsigned int rh1  = mapa_u32(smem_u32(&h_buf[1][j]), peer);
    const unsigned int rmb0 = mapa_u32(mb0, peer);
    const unsigned int rmb1 = mapa_u32(mb1, peer);

    const float* gi   = &g_gi[dir][0][0];
    float*       hout = &g_hout[dir][0][0];
    const int tstep = dir ? -1 : 1;
    int t = dir ? (T_LEN - 1) : 0;
    float g_cur = (half == 0) ? __ldg(gi + t * G3 + grow) : 0.0f;

    for (int s = 0; s < T_LEN; s++) {
        const unsigned int mb_cur  = (s & 1) ? mb1 : mb0;
        const unsigned int rmb_cur = (s & 1) ? rmb1 : rmb0;
        if (tid == 0) mbar_arrive_expect_tx(mb_cur, 256);

        float g_next = 0.0f;
        if (half == 0 && s + 1 < T_LEN)
            g_next = __ldg(gi + (t + tstep) * G3 + grow);

        // half-dot: 32 packed f32x2 FMAs over my 64-slice of h
        unsigned long long a0 = pack2(bias, 0.0f);
        unsigned long long a1 = 0ull, a2 = 0ull, a3 = 0ull;
        const ulonglong2* h2 =
            reinterpret_cast<const ulonglong2*>(&h_buf[s & 1][half * 64]);
#pragma unroll
        for (int q = 0; q < 8; q++) {
            ulonglong2 v0 = h2[2 * q];
            ulonglong2 v1 = h2[2 * q + 1];
            a0 = ffma2(w[4 * q + 0], v0.x, a0);
            a1 = ffma2(w[4 * q + 1], v0.y, a1);
            a2 = ffma2(w[4 * q + 2], v1.x, a2);
            a3 = ffma2(w[4 * q + 3], v1.y, a3);
        }
        float2 f0 = unpack2(a0), f1 = unpack2(a1);
        float2 f2 = unpack2(a2), f3 = unpack2(a3);
        float part = ((f0.x + f0.y) + (f1.x + f1.y)) +
                     ((f2.x + f2.y) + (f3.x + f3.y));
        float gh = part + __shfl_xor_sync(0xFFFFFFFFu, part, 1);

        if (half == 0) {
            if (gate == 0)       r_s[jj] = sigmoidf_(g_cur + gh);
            else if (gate == 1)  z_s[jj] = sigmoidf_(g_cur + gh);
        }
        __syncthreads();                       // bar A: r/z ready, h reads done
        if (half == 0 && gate == 2) {
            float n    = tanhf(g_cur + r_s[jj] * gh);
            float hold = h_buf[s & 1][j];
            float hnew = n + z_s[jj] * (hold - n);     // (1-z)*n + z*h
            h_buf[(s + 1) & 1][j] = hnew;
            hout[t * HID + j] = hnew;
            st_async_remote_f32(((s + 1) & 1) ? rh1 : rh0, hnew, rmb_cur);
        }
        __syncthreads();                       // bar B: local h half visible
        // only consumers of the REMOTE half (plus tid0, which must pace the
        // mbarrier) wait; local-half threads start next step's FMAs early.
        if ((unsigned)half != rank || tid == 0)
            mbar_wait_parity(mb_cur, (s >> 1) & 1);

        g_cur = g_next;
        t += tstep;
    }
    cluster_sync_();
}

// ============ Kernel 3: output projection + softmax (per timestep) ========
__global__ void __launch_bounds__(192) proj_kernel(
    const float* __restrict__ W_out, const float* __restrict__ b_out)
{
    const int t    = blockIdx.x;
    const int wid  = threadIdx.x >> 5;   // state 0..5
    const int lane = threadIdx.x & 31;
    __shared__ float lg_s[NS];

    float acc = 0.0f;
    const float* Wr = W_out + wid * (2 * HID);
#pragma unroll
    for (int i = lane; i < 2 * HID; i += 32) {
        float c = (i < HID) ? g_hout[0][t][i] : g_hout[1][t][i - HID];
        acc += c * __ldg(Wr + i);
    }
#pragma unroll
    for (int off = 16; off; off >>= 1)
        acc += __shfl_xor_sync(0xFFFFFFFFu, acc, off);
    if (lane == 0) lg_s[wid] = acc + b_out[wid];
    __syncthreads();

    if (threadIdx.x == 0) {
        float m = lg_s[0];
#pragma unroll
        for (int i = 1; i < NS; i++) m = fmaxf(m, lg_s[i]);
        float e[NS];
        float sum = 0.0f;
#pragma unroll
        for (int i = 0; i < NS; i++) { e[i] = expf(lg_s[i] - m); sum += e[i]; }
        float inv = 1.0f / sum;
#pragma unroll
        for (int i = 0; i < NS; i++) g_logits[t * NS + i] = e[i] * inv;
    }
}

// ================= Kernel 4: Viterbi (1 warp, exact ops) ==================
// Forward: max-tree (exact) + equality first-argmax; backpointers packed as
// 6-nibble integer maps. Backtrack: parallel suffix composition of maps
// (bit-exact — integer composition).
__global__ void viterbi_kernel(const float* __restrict__ transitions,
                               float* __restrict__ out, int out_size)
{
    extern __shared__ char sm[];
    float*        lg_sh = (float*)sm;                         // T*6 floats
    unsigned int* mp_sh = (unsigned int*)(sm + T_LEN * NS * 4); // T-1 maps
    const int lane = threadIdx.x;

    {   // stage logits into SMEM
        const float4* src = (const float4*)g_logits;
        float4*       dst = (float4*)lg_sh;
        for (int i = lane; i < T_LEN * NS / 4; i += 32) dst[i] = src[i];
    }
    __syncwarp();

    float Tc[NS];
#pragma unroll
    for (int i = 0; i < NS; i++)
        Tc[i] = (lane < NS) ? transitions[i * NS + lane] : 0.0f;

    const int l6 = (lane < NS) ? lane : 0;
    float tr = (lane < NS) ? lg_sh[lane] : -1e30f;

    for (int t = 1; t < T_LEN; t++) {
        float lgv = lg_sh[t * NS + l6];
        float v0 = __shfl_sync(0xFFFFFFFFu, tr, 0) + Tc[0];
        float v1 = __shfl_sync(0xFFFFFFFFu, tr, 1) + Tc[1];
        float v2 = __shfl_sync(0xFFFFFFFFu, tr, 2) + Tc[2];
        float v3 = __shfl_sync(0xFFFFFFFFu, tr, 3) + Tc[3];
        float v4 = __shfl_sync(0xFFFFFFFFu, tr, 4) + Tc[4];
        float v5 = __shfl_sync(0xFFFFFFFFu, tr, 5) + Tc[5];
        float m  = fmaxf(fmaxf(fmaxf(v0, v1), fmaxf(v2, v3)), fmaxf(v4, v5));
        int bi = (v0 == m) ? 0 : (v1 == m) ? 1 : (v2 == m) ? 2 :
                 (v3 == m) ? 3 : (v4 == m) ? 4 : 5;     // first argmax (exact)
        if (lane < NS) tr = lgv + m;
        unsigned int pv = (lane < NS) ? ((unsigned int)bi << (4 * lane)) : 0u;
        pv |= __shfl_xor_sync(0xFFFFFFFFu, pv, 1);
        pv |= __shfl_xor_sync(0xFFFFFFFFu, pv, 2);
        pv |= __shfl_xor_sync(0xFFFFFFFFu, pv, 4);
        if (lane == 0) mp_sh[t - 1] = pv;
    }

    // final score + first-argmax (exact)
    float f0 = __shfl_sync(0xFFFFFFFFu, tr, 0);
    float f1 = __shfl_sync(0xFFFFFFFFu, tr, 1);
    float f2 = __shfl_sync(0xFFFFFFFFu, tr, 2);
    float f3 = __shfl_sync(0xFFFFFFFFu, tr, 3);
    float f4 = __shfl_sync(0xFFFFFFFFu, tr, 4);
    float f5 = __shfl_sync(0xFFFFFFFFu, tr, 5);
    float score = fmaxf(fmaxf(fmaxf(f0, f1), fmaxf(f2, f3)), fmaxf(f4, f5));
    int last = (f0 == score) ? 0 : (f1 == score) ? 1 : (f2 == score) ? 2 :
               (f3 == score) ? 3 : (f4 == score) ? 4 : 5;
    if (lane == 0) out[0] = score;
    __syncwarp();

    // ---- parallel backtrack: 32 chunks x 64 steps, nibble maps ----
    const unsigned int IDENT = 0x00543210u;
    unsigned int mp_loc[64];
#pragma unroll
    for (int s2 = 0; s2 < 64; s2++) {
        int k = lane * 64 + s2;
        mp_loc[s2] = (k <= T_LEN - 2) ? mp_sh[k] : IDENT;
    }
    // chunk map C = bp_k0 o bp_k0+1 o ... (apply high t first)
    unsigned int M = IDENT;
#pragma unroll
    for (int s2 = 63; s2 >= 0; s2--) {
        unsigned int f = mp_loc[s2];
        unsigned int Mn = 0;
#pragma unroll
        for (int jq = 0; jq < 6; jq++) {
            unsigned int y = (M >> (4 * jq)) & 15u;
            Mn |= ((f >> (4 * y)) & 15u) << (4 * jq);
        }
        M = Mn;
    }
    // inclusive suffix scan: S_c = C_c o C_{c+1} o ... o C_31
    unsigned int S = M;
#pragma unroll
    for (int d = 1; d < 32; d <<= 1) {
        unsigned int other = __shfl_down_sync(0xFFFFFFFFu, S, d);
        if (lane + d < 32) {
            unsigned int Sn = 0;
#pragma unroll
            for (int jq = 0; jq < 6; jq++) {
                unsigned int y = (other >> (4 * jq)) & 15u;
                Sn |= ((S >> (4 * y)) & 15u) << (4 * jq);
            }
            S = Sn;
        }
    }
    unsigned int Snext = __shfl_down_sync(0xFFFFFFFFu, S, 1);
    int cur = (lane == 31) ? last : (int)((Snext >> (4 * last)) & 15u);
#pragma unroll
    for (int s2 = 63; s2 >= 0; s2--) {
        int k = lane * 64 + s2;
        if (k <= T_LEN - 2) {
            cur = (int)((mp_loc[s2] >> (4 * cur)) & 15u);
            out[1 + k] = (float)cur;
        }
    }
    if (lane == 31) out[1 + T_LEN - 1] = (float)last;
    for (int i = T_LEN + 1 + lane; i < out_size; i += 32) out[i] = 0.0f;
}

// ============================ launch =======================================
extern "C" void kernel_launch(void* const* d_in, const int* in_sizes, int n_in,
                              void* d_out, int out_size) {
    const int*   sentence    = (const int*)d_in[0];
    const float* emb         = (const float*)d_in[1];
    const float* h0          = (const float*)d_in[2];
    const float* Wf_ih       = (const float*)d_in[3];
    const float* Wf_hh       = (const float*)d_in[4];
    const float* bf_ih       = (const float*)d_in[5];
    const float* bf_hh       = (const float*)d_in[6];
    const float* Wb_ih       = (const float*)d_in[7];
    const float* Wb_hh       = (const float*)d_in[8];
    const float* bb_ih       = (const float*)d_in[9];
    const float* bb_hh       = (const float*)d_in[10];
    const float* W_out       = (const float*)d_in[11];
    const float* b_out       = (const float*)d_in[12];
    const float* transitions = (const float*)d_in[13];
    float*       out         = (float*)d_out;

    const int vit_smem = T_LEN * NS * 4 + (T_LEN - 1) * 4;  // 57340 B
    cudaFuncSetAttribute(viterbi_kernel,
                         cudaFuncAttributeMaxDynamicSharedMemorySize, vit_smem);

    gi_kernel<<<dim3(T_LEN / 4, 2), G3>>>(sentence, emb, Wf_ih, bf_ih,
                                          Wb_ih, bb_ih);
    gru_kernel<<<4, GRU_THREADS>>>(Wf_hh, bf_hh, Wb_hh, bb_hh, h0);
    proj_kernel<<<T_LEN, 192>>>(W_out, b_out);
    viterbi_kernel<<<1, 32, vit_smem>>>(transitions, out, out_size);
}

// round 3
// speedup vs baseline: 1.5807x; 1.5807x over previous
#include <cuda_runtime.h>
#include <math.h>

#define T_LEN 2048
#define BATCH 64
#define EMB   100
#define HID   128
#define G3    384   // 3*HID gate rows
#define NS    6     // CRF states

// ---------------- device scratch (no allocation allowed) ----------------
__device__ float g_gi[2][T_LEN][G3];        // precomputed x@Wih^T + bih, per dir
__device__ float g_hout[2][T_LEN][HID];     // GRU hidden outputs, per dir
__device__ __align__(16) float g_logits[T_LEN * NS];  // softmax probs

// ---------------- f32x2 helpers (packed dual-FP32 FMA, sm_100+) ---------
__device__ __forceinline__ unsigned long long ffma2(unsigned long long a,
                                                    unsigned long long b,
                                                    unsigned long long c) {
    unsigned long long d;
    asm("fma.rn.f32x2 %0, %1, %2, %3;" : "=l"(d) : "l"(a), "l"(b), "l"(c));
    return d;
}
__device__ __forceinline__ unsigned long long pack2(float lo, float hi) {
    unsigned long long d;
    asm("mov.b64 %0, {%1, %2};" : "=l"(d) : "f"(lo), "f"(hi));
    return d;
}
__device__ __forceinline__ float2 unpack2(unsigned long long u) {
    float2 r;
    asm("mov.b64 {%0, %1}, %2;" : "=f"(r.x), "=f"(r.y) : "l"(u));
    return r;
}
__device__ __forceinline__ float sigmoidf_(float x) {
    return 1.0f / (1.0f + expf(-x));
}

// ================= Kernel 1: gi = x @ Wih^T + bih (batch row 63) =========
// grid (256, 2), block 384. Each block: 8 timesteps for one direction.
__global__ void __launch_bounds__(G3) gi_kernel(
    const int* __restrict__ sentence, const float* __restrict__ emb,
    const float* __restrict__ Wf_ih, const float* __restrict__ bf_ih,
    const float* __restrict__ Wb_ih, const float* __restrict__ bb_ih)
{
    const int dir = blockIdx.y;
    const int t0  = blockIdx.x * 8;
    __shared__ float x_s[8][EMB];

    for (int i = threadIdx.x; i < 8 * EMB; i += G3) {
        int tt = i / EMB, e = i % EMB;
        int tok = sentence[63 * T_LEN + t0 + tt];
        x_s[tt][e] = emb[tok * EMB + e];
    }
    __syncthreads();

    const float* W = dir ? Wb_ih : Wf_ih;
    const float* b = dir ? bb_ih : bf_ih;
    const int j = threadIdx.x;

    float bj = b[j];
    float acc[8];
#pragma unroll
    for (int q = 0; q < 8; q++) acc[q] = bj;
    const float* Wr = W + j * EMB;
#pragma unroll
    for (int e = 0; e < EMB; e++) {
        float w = __ldg(Wr + e);
#pragma unroll
        for (int q = 0; q < 8; q++) acc[q] += w * x_s[q][e];
    }
#pragma unroll
    for (int q = 0; q < 8; q++) g_gi[dir][t0 + q][j] = acc[q];
}

// ================= Kernel 2: sequential GRU recurrence ====================
// grid 2 (direction), block 384 (one gate-row per thread).
// Named-barrier split: r/z warps arrive B1 (non-blocking), n warps wait B1;
// everyone syncs B2 after the double-buffered h update.
__global__ void __launch_bounds__(G3, 1) gru_kernel(
    const float* __restrict__ Wf_hh, const float* __restrict__ bf_hh,
    const float* __restrict__ Wb_hh, const float* __restrict__ bb_hh,
    const float* __restrict__ h0)
{
    const int dir  = blockIdx.x;
    const int j    = threadIdx.x;      // gate row 0..383
    const int gate = j >> 7;           // 0=r, 1=z, 2=n
    const int unit = j & 127;

    __shared__ __align__(16) float h_buf[2][HID];
    __shared__ float r_s[HID];
    __shared__ float z_s[HID];

    const float* Whh = dir ? Wb_hh : Wf_hh;
    const float* bhh = dir ? bb_hh : bf_hh;

    // weight row j as 64 packed f32x2 registers
    unsigned long long w[64];
    {
        const unsigned long long* Wrow =
            reinterpret_cast<const unsigned long long*>(Whh + j * HID);
#pragma unroll
        for (int k = 0; k < 64; k++) w[k] = __ldg(Wrow + k);
    }
    const float bias = bhh[j];

    if (j < HID) h_buf[0][j] = h0[dir * (BATCH * HID) + 63 * HID + j];
    __syncthreads();

    const float* gi   = &g_gi[dir][0][0];
    float*       hout = &g_hout[dir][0][0];

    const int tstep = dir ? -1 : 1;
    int t = dir ? (T_LEN - 1) : 0;
    float g_cur = __ldg(gi + t * G3 + j);

    for (int s = 0; s < T_LEN; s++) {
        const int p = s & 1;
        // prefetch next step's gi (hidden under the dot)
        float g_next = 0.0f;
        if (s + 1 < T_LEN) g_next = __ldg(gi + (t + tstep) * G3 + j);

        // gh_j = Whh[j,:] . h + bhh[j]   (packed dual-FP32 FMAs)
        unsigned long long a0 = pack2(bias, 0.0f);
        unsigned long long a1 = 0ull, a2 = 0ull, a3 = 0ull;
        const ulonglong2* h2 = reinterpret_cast<const ulonglong2*>(h_buf[p]);
#pragma unroll
        for (int q = 0; q < 16; q++) {
            ulonglong2 hv0 = h2[2 * q];
            ulonglong2 hv1 = h2[2 * q + 1];
            a0 = ffma2(w[4 * q + 0], hv0.x, a0);
            a1 = ffma2(w[4 * q + 1], hv0.y, a1);
            a2 = ffma2(w[4 * q + 2], hv1.x, a2);
            a3 = ffma2(w[4 * q + 3], hv1.y, a3);
        }
        float2 f0 = unpack2(a0), f1 = unpack2(a1);
        float2 f2 = unpack2(a2), f3 = unpack2(a3);
        float gh = ((f0.x + f0.y) + (f1.x + f1.y)) +
                   ((f2.x + f2.y) + (f3.x + f3.y));

        if (gate == 0) {                 // r gate: produce, arrive, move on
            r_s[unit] = sigmoidf_(g_cur + gh);
            asm volatile("bar.arrive 1, 384;" ::: "memory");
        } else if (gate == 1) {          // z gate
            z_s[unit] = sigmoidf_(g_cur + gh);
            asm volatile("bar.arrive 1, 384;" ::: "memory");
        } else {                         // n gate: wait for r/z, update state
            asm volatile("bar.sync 1, 384;" ::: "memory");
            float n    = tanhf(g_cur + r_s[unit] * gh);
            float hold = h_buf[p][unit];
            float hnew = n + z_s[unit] * (hold - n);   // (1-z)*n + z*h
            h_buf[p ^ 1][unit] = hnew;
            hout[t * HID + unit] = hnew;
        }
        asm volatile("bar.sync 2, 384;" ::: "memory");  // h(p^1) ready

        g_cur = g_next;
        t += tstep;
    }
}

// ============ Kernel 3: output projection + softmax (per timestep) ========
__global__ void __launch_bounds__(192) proj_kernel(
    const float* __restrict__ W_out, const float* __restrict__ b_out)
{
    const int t    = blockIdx.x;
    const int wid  = threadIdx.x >> 5;   // state 0..5
    const int lane = threadIdx.x & 31;
    __shared__ float lg_s[NS];

    float acc = 0.0f;
    const float* Wr = W_out + wid * (2 * HID);
#pragma unroll
    for (int i = lane; i < 2 * HID; i += 32) {
        float c = (i < HID) ? g_hout[0][t][i] : g_hout[1][t][i - HID];
        acc += c * __ldg(Wr + i);
    }
#pragma unroll
    for (int off = 16; off; off >>= 1)
        acc += __shfl_xor_sync(0xFFFFFFFFu, acc, off);
    if (lane == 0) lg_s[wid] = acc + b_out[wid];
    __syncthreads();

    if (threadIdx.x == 0) {
        float m = lg_s[0];
#pragma unroll
        for (int i = 1; i < NS; i++) m = fmaxf(m, lg_s[i]);
        float e[NS];
        float sum = 0.0f;
#pragma unroll
        for (int i = 0; i < NS; i++) { e[i] = expf(lg_s[i] - m); sum += e[i]; }
        float inv = 1.0f / sum;
#pragma unroll
        for (int i = 0; i < NS; i++) g_logits[t * NS + i] = e[i] * inv;
    }
}

// ================= Kernel 4: Viterbi (1 warp) =============================
// Forward: pair-max tree (exact, >= keeps left => first argmax), byte bp
// stores (no cross-lane packing). Backtrack: lane-parallel nibble-map
// suffix composition (bit-exact integer ops).
__global__ void viterbi_kernel(const float* __restrict__ transitions,
                               float* __restrict__ out, int out_size)
{
    extern __shared__ char sm[];
    float*         lg_sh = (float*)sm;                        // T*6 floats
    unsigned char* bp8   = (unsigned char*)(sm + T_LEN * NS * 4); // (T-1)*8
    const int lane = threadIdx.x;

    {   // stage logits into SMEM
        const float4* src = (const float4*)g_logits;
        float4*       dst = (float4*)lg_sh;
        for (int i = lane; i < T_LEN * NS / 4; i += 32) dst[i] = src[i];
    }
    __syncwarp();

    float Tc[NS];
#pragma unroll
    for (int i = 0; i < NS; i++)
        Tc[i] = (lane < NS) ? transitions[i * NS + lane] : 0.0f;

    const int l6 = (lane < NS) ? lane : 0;
    float tr = (lane < NS) ? lg_sh[lane] : -1e30f;

    for (int t = 1; t < T_LEN; t++) {
        float lgv = lg_sh[t * NS + l6];
        float v0 = __shfl_sync(0xFFFFFFFFu, tr, 0) + Tc[0];
        float v1 = __shfl_sync(0xFFFFFFFFu, tr, 1) + Tc[1];
        float v2 = __shfl_sync(0xFFFFFFFFu, tr, 2) + Tc[2];
        float v3 = __shfl_sync(0xFFFFFFFFu, tr, 3) + Tc[3];
        float v4 = __shfl_sync(0xFFFFFFFFu, tr, 4) + Tc[4];
        float v5 = __shfl_sync(0xFFFFFFFFu, tr, 5) + Tc[5];
        // depth-3 pair tree, ties keep the left (= smaller index)
        float m01 = fmaxf(v0, v1);  int i01 = (v0 >= v1) ? 0 : 1;
        float m23 = fmaxf(v2, v3);  int i23 = (v2 >= v3) ? 2 : 3;
        float m45 = fmaxf(v4, v5);  int i45 = (v4 >= v5) ? 4 : 5;
        float m03 = fmaxf(m01, m23); int i03 = (m01 >= m23) ? i01 : i23;
        float m   = fmaxf(m03, m45); int bi  = (m03 >= m45) ? i03 : i45;
        if (lane < NS) {
            tr = lgv + m;
            bp8[(t - 1) * 8 + lane] = (unsigned char)bi;
        }
    }

    // final score + first-argmax via the same exact tree
    float f0 = __shfl_sync(0xFFFFFFFFu, tr, 0);
    float f1 = __shfl_sync(0xFFFFFFFFu, tr, 1);
    float f2 = __shfl_sync(0xFFFFFFFFu, tr, 2);
    float f3 = __shfl_sync(0xFFFFFFFFu, tr, 3);
    float f4 = __shfl_sync(0xFFFFFFFFu, tr, 4);
    float f5 = __shfl_sync(0xFFFFFFFFu, tr, 5);
    float n01 = fmaxf(f0, f1);  int k01 = (f0 >= f1) ? 0 : 1;
    float n23 = fmaxf(f2, f3);  int k23 = (f2 >= f3) ? 2 : 3;
    float n45 = fmaxf(f4, f5);  int k45 = (f4 >= f5) ? 4 : 5;
    float n03 = fmaxf(n01, n23); int k03 = (n01 >= n23) ? k01 : k23;
    float score = fmaxf(n03, n45); int last = (n03 >= n45) ? k03 : k45;
    if (lane == 0) out[0] = score;
    __syncwarp();

    // ---- parallel backtrack: 32 chunks x 64 steps, nibble maps ----
    const unsigned int IDENT = 0x00543210u;
    unsigned int mp_loc[64];
#pragma unroll
    for (int s2 = 0; s2 < 64; s2++) {
        int k = lane * 64 + s2;
        if (k <= T_LEN - 2) {
            unsigned long long f8 =
                *reinterpret_cast<const unsigned long long*>(&bp8[k * 8]);
            unsigned int lo = (unsigned int)f8;
            unsigned int hi = (unsigned int)(f8 >> 32);
            mp_loc[s2] = (lo & 0xFu) | ((lo >> 4) & 0xF0u) |
                         ((lo >> 8) & 0xF00u) | ((lo >> 12) & 0xF000u) |
                         ((hi & 0xFu) << 16) | (((hi >> 8) & 0xFu) << 20);
        } else {
            mp_loc[s2] = IDENT;
        }
    }
    // chunk map C = f_k0 o f_k0+1 o ... (apply highest k first)
    unsigned int M = IDENT;
#pragma unroll
    for (int s2 = 63; s2 >= 0; s2--) {
        unsigned int f = mp_loc[s2];
        unsigned int Mn = 0;
#pragma unroll
        for (int jq = 0; jq < 6; jq++) {
            unsigned int y = (M >> (4 * jq)) & 15u;
            Mn |= ((f >> (4 * y)) & 15u) << (4 * jq);
        }
        M = Mn;
    }
    // inclusive suffix scan: S_c = C_c o C_{c+1} o ... o C_31
    unsigned int S = M;
#pragma unroll
    for (int d = 1; d < 32; d <<= 1) {
        unsigned int other = __shfl_down_sync(0xFFFFFFFFu, S, d);
        if (lane + d < 32) {
            unsigned int Sn = 0;
#pragma unroll
            for (int jq = 0; jq < 6; jq++) {
                unsigned int y = (other >> (4 * jq)) & 15u;
                Sn |= ((S >> (4 * y)) & 15u) << (4 * jq);
            }
            S = Sn;
        }
    }
    unsigned int Snext = __shfl_down_sync(0xFFFFFFFFu, S, 1);
    int cur = (lane == 31) ? last : (int)((Snext >> (4 * last)) & 15u);
#pragma unroll
    for (int s2 = 63; s2 >= 0; s2--) {
        int k = lane * 64 + s2;
        if (k <= T_LEN - 2) {
            cur = (int)((mp_loc[s2] >> (4 * cur)) & 15u);
            out[1 + k] = (float)cur;
        }
    }
    if (lane == 31) out[1 + T_LEN - 1] = (float)last;
    for (int i = T_LEN + 1 + lane; i < out_size; i += 32) out[i] = 0.0f;
}

// ============================ launch =======================================
extern "C" void kernel_launch(void* const* d_in, const int* in_sizes, int n_in,
                              void* d_out, int out_size) {
    const int*   sentence    = (const int*)d_in[0];
    const float* emb         = (const float*)d_in[1];
    const float* h0          = (const float*)d_in[2];
    const float* Wf_ih       = (const float*)d_in[3];
    const float* Wf_hh       = (const float*)d_in[4];
    const float* bf_ih       = (const float*)d_in[5];
    const float* bf_hh       = (const float*)d_in[6];
    const float* Wb_ih       = (const float*)d_in[7];
    const float* Wb_hh       = (const float*)d_in[8];
    const float* bb_ih       = (const float*)d_in[9];
    const float* bb_hh       = (const float*)d_in[10];
    const float* W_out       = (const float*)d_in[11];
    const float* b_out       = (const float*)d_in[12];
    const float* transitions = (const float*)d_in[13];
    float*       out         = (float*)d_out;

    const int vit_smem = T_LEN * NS * 4 + (T_LEN - 1) * 8;  // 65528 B
    cudaFuncSetAttribute(viterbi_kernel,
                         cudaFuncAttributeMaxDynamicSharedMemorySize, vit_smem);

    gi_kernel<<<dim3(T_LEN / 8, 2), G3>>>(sentence, emb, Wf_ih, bf_ih,
                                          Wb_ih, bb_ih);
    gru_kernel<<<2, G3>>>(Wf_hh, bf_hh, Wb_hh, bb_hh, h0);
    proj_kernel<<<T_LEN, 192>>>(W_out, b_out);
    viterbi_kernel<<<1, 32, vit_smem>>>(transitions, out, out_size);
}